// round 1
// baseline (speedup 1.0000x reference)
#include <cuda_runtime.h>

typedef unsigned long long u64;

#define SEQ   4096
#define BATCH 2
#define EMB   768
#define NHEAD 12
#define HDIM  64
#define HALFW 256

// scratch: q, k, v in (B, H, S, D) layout. 3 * 25.2 MB
__device__ float g_qkv[3][(size_t)BATCH * NHEAD * SEQ * HDIM];

// ---------------- packed f32x2 helpers (ptxas never auto-fuses these) -------
__device__ __forceinline__ u64 pack2(float lo, float hi) {
    u64 r;
    asm("mov.b64 %0, {%1, %2};" : "=l"(r) : "f"(lo), "f"(hi));
    return r;
}
__device__ __forceinline__ void unpack2(u64 v, float& lo, float& hi) {
    asm("mov.b64 {%0, %1}, %2;" : "=f"(lo), "=f"(hi) : "l"(v));
}
__device__ __forceinline__ void fma2(u64& d, u64 a, u64 b) {
    asm("fma.rn.f32x2 %0, %1, %2, %0;" : "+l"(d) : "l"(a), "l"(b));
}

// ---------------------------------------------------------------------------
// Kernel 1: QKV projection.
//   dst[b,h,s,d] = (sum_e query[s,b,e] * W[e, h*64+d] + bias[h*64+d]) * scale
// grid = (M/64, N/64, 3), block = 256 (16x16 threads, 4x4 microtile)
// f32x2 packed accumulation: acc[i][p] holds output cols (4tx+2p, 4tx+2p+1)
// ---------------------------------------------------------------------------
__global__ __launch_bounds__(256) void qkv_gemm_kernel(
    const float* __restrict__ X,
    const float* __restrict__ Wq, const float* __restrict__ bq,
    const float* __restrict__ Wk, const float* __restrict__ bk,
    const float* __restrict__ Wv, const float* __restrict__ bv)
{
    __shared__ __align__(16) float a_s[64][33];  // a_s[m][kk], stride 33 (odd): conflict-free
    __shared__ __align__(16) float b_s[32][66];  // b_s[kk][n],  stride 66: 8B-aligned rows

    const int which = blockIdx.z;
    const float* W    = (which == 0) ? Wq : (which == 1) ? Wk : Wv;
    const float* bias = (which == 0) ? bq : (which == 1) ? bk : bv;
    float* dst = g_qkv[which];
    const float scale = (which == 0) ? 0.125f : 1.0f;  // 1/sqrt(64) on q

    const int tid = threadIdx.x;
    const int ty = tid >> 4;          // 0..15 -> rows 4ty..4ty+3
    const int tx = tid & 15;          // 0..15 -> cols 4tx..4tx+3
    const int m0 = blockIdx.x * 64;   // m = b*SEQ + s
    const int n0 = blockIdx.y * 64;

    u64 acc[4][2];
#pragma unroll
    for (int i = 0; i < 4; i++) { acc[i][0] = 0ull; acc[i][1] = 0ull; }

    for (int k0 = 0; k0 < EMB; k0 += 32) {
        // stage A: rows m0..m0+63, cols k0..k0+31 (coalesced float4 loads)
        {
            const int r = tid >> 3;   // 0..31
            const int c = tid & 7;    // 0..7 float4 within 32 cols
#pragma unroll
            for (int pp = 0; pp < 2; pp++) {
                const int row = r + 32 * pp;
                const int m = m0 + row;
                const int bb = m >> 12;
                const int ss = m & 4095;
                const float4 v = *(const float4*)(X + ((size_t)ss * BATCH + bb) * EMB + k0 + c * 4);
                a_s[row][c * 4 + 0] = v.x;
                a_s[row][c * 4 + 1] = v.y;
                a_s[row][c * 4 + 2] = v.z;
                a_s[row][c * 4 + 3] = v.w;
            }
        }
        // stage B: W rows k0..k0+31, cols n0..n0+63
        {
            const int r  = tid >> 4;  // 0..15
            const int c4 = tid & 15;
#pragma unroll
            for (int pp = 0; pp < 2; pp++) {
                const int row = r + 16 * pp;
                const float4 v = *(const float4*)(W + (size_t)(k0 + row) * EMB + n0 + c4 * 4);
                b_s[row][c4 * 4 + 0] = v.x;
                b_s[row][c4 * 4 + 1] = v.y;
                b_s[row][c4 * 4 + 2] = v.z;
                b_s[row][c4 * 4 + 3] = v.w;
            }
        }
        __syncthreads();

#pragma unroll 8
        for (int kk = 0; kk < 32; kk++) {
            const u64 bv0 = *(const u64*)&b_s[kk][tx * 4];      // cols 4tx,4tx+1
            const u64 bv1 = *(const u64*)&b_s[kk][tx * 4 + 2];  // cols 4tx+2,4tx+3
#pragma unroll
            for (int i = 0; i < 4; i++) {
                const float a = a_s[ty * 4 + i][kk];
                const u64 aa = pack2(a, a);
                fma2(acc[i][0], aa, bv0);
                fma2(acc[i][1], aa, bv1);
            }
        }
        __syncthreads();
    }

    // epilogue: (acc + bias) * scale  ->  dst[(b*H + h)*S*D + s*D + d]
    const int h = n0 >> 6;  // tile spans exactly one head (64 cols)
    float bvals[4];
#pragma unroll
    for (int j = 0; j < 4; j++) bvals[j] = bias[n0 + tx * 4 + j];

#pragma unroll
    for (int i = 0; i < 4; i++) {
        const int m = m0 + ty * 4 + i;
        const int bb = m >> 12;
        const int ss = m & 4095;
        float v0, v1, v2, v3;
        unpack2(acc[i][0], v0, v1);
        unpack2(acc[i][1], v2, v3);
        float4 o;
        o.x = (v0 + bvals[0]) * scale;
        o.y = (v1 + bvals[1]) * scale;
        o.z = (v2 + bvals[2]) * scale;
        o.w = (v3 + bvals[3]) * scale;
        *(float4*)(dst + ((size_t)(bb * NHEAD + h) * SEQ + ss) * HDIM + tx * 4) = o;
    }
}

// ---------------------------------------------------------------------------
// Kernel 2: banded local attention, flash-style online softmax.
// Block = 64 queries of one (b,h). Key tiles of 32, window [q0-256, q0+319].
// Thread grid 16x16: scores microtile 4 rows x 2 keys; output 4 rows x 4 dims.
// grid = (S/64, H, B), block = 256.
// ---------------------------------------------------------------------------
__global__ __launch_bounds__(256) void attn_kernel(float* __restrict__ out)
{
    __shared__ __align__(16) float q_s[64][64];  // q_s[q][d]  (reads broadcast by ty)
    __shared__ __align__(16) float k_s[32][65];  // k_s[key][d], odd stride: column reads conflict-free
    __shared__ __align__(16) float v_s[32][64];  // v_s[key][d]
    __shared__ __align__(16) float p_s[64][32];  // p_s[q][key]

    const int tid = threadIdx.x;
    const int ty = tid >> 4;   // row group
    const int tx = tid & 15;   // key/dim group
    const int q0 = blockIdx.x * 64;
    const int h  = blockIdx.y;
    const int b  = blockIdx.z;

    const size_t bh = (size_t)(b * NHEAD + h) * SEQ * HDIM;
    const float* qg = g_qkv[0] + bh;
    const float* kg = g_qkv[1] + bh;
    const float* vg = g_qkv[2] + bh;

    // load Q tile once (64 rows x 16 float4)
    for (int idx = tid; idx < 64 * 16; idx += 256) {
        const int row = idx >> 4;
        const int c4  = idx & 15;
        *(float4*)&q_s[row][c4 * 4] = *(const float4*)(qg + (size_t)(q0 + row) * HDIM + c4 * 4);
    }

    float o[4][4];
    float m_r[4], l_r[4];
#pragma unroll
    for (int i = 0; i < 4; i++) {
        m_r[i] = -1e30f;
        l_r[i] = 0.0f;
#pragma unroll
        for (int j = 0; j < 4; j++) o[i][j] = 0.0f;
    }

    for (int kt = q0 - HALFW; kt <= q0 + 288; kt += 32) {
        if (kt < 0 || kt >= SEQ) continue;  // 32-aligned tiles: fully in or fully out
        __syncthreads();
        // stage K and V tiles (32 keys x 64 dims)
        for (int idx = tid; idx < 32 * 16; idx += 256) {
            const int row = idx >> 4;
            const int c4  = idx & 15;
            const float4 kv = *(const float4*)(kg + (size_t)(kt + row) * HDIM + c4 * 4);
            k_s[row][c4 * 4 + 0] = kv.x;
            k_s[row][c4 * 4 + 1] = kv.y;
            k_s[row][c4 * 4 + 2] = kv.z;
            k_s[row][c4 * 4 + 3] = kv.w;
            *(float4*)&v_s[row][c4 * 4] = *(const float4*)(vg + (size_t)(kt + row) * HDIM + c4 * 4);
        }
        __syncthreads();

        // scores: S[4 rows][2 keys] = Q . K^T
        float sc[4][2];
#pragma unroll
        for (int i = 0; i < 4; i++) { sc[i][0] = 0.0f; sc[i][1] = 0.0f; }
#pragma unroll 8
        for (int kk = 0; kk < HDIM; kk++) {
            const float kv0 = k_s[tx * 2 + 0][kk];
            const float kv1 = k_s[tx * 2 + 1][kk];
#pragma unroll
            for (int i = 0; i < 4; i++) {
                const float qv = q_s[ty * 4 + i][kk];
                sc[i][0] += qv * kv0;
                sc[i][1] += qv * kv1;
            }
        }

        // band mask + online softmax (rows reduced across the 16 tx lanes)
#pragma unroll
        for (int i = 0; i < 4; i++) {
            const int qa = q0 + ty * 4 + i;
#pragma unroll
            for (int j = 0; j < 2; j++) {
                const int d = (kt + tx * 2 + j) - qa;
                if (d < -HALFW || d > HALFW) sc[i][j] = -3.0e38f;
            }
            float tmax = fmaxf(sc[i][0], sc[i][1]);
#pragma unroll
            for (int off = 1; off < 16; off <<= 1)
                tmax = fmaxf(tmax, __shfl_xor_sync(0xffffffffu, tmax, off));
            const float newm = fmaxf(m_r[i], tmax);
            const float corr = __expf(m_r[i] - newm);
            const float p0 = __expf(sc[i][0] - newm);
            const float p1 = __expf(sc[i][1] - newm);
            float rs = p0 + p1;
#pragma unroll
            for (int off = 1; off < 16; off <<= 1)
                rs += __shfl_xor_sync(0xffffffffu, rs, off);
            l_r[i] = l_r[i] * corr + rs;
            m_r[i] = newm;
#pragma unroll
            for (int j2 = 0; j2 < 4; j2++) o[i][j2] *= corr;
            p_s[ty * 4 + i][tx * 2 + 0] = p0;
            p_s[ty * 4 + i][tx * 2 + 1] = p1;
        }
        __syncthreads();

        // O += P . V
#pragma unroll 8
        for (int c = 0; c < 32; c++) {
            const float v0 = v_s[c][tx * 4 + 0];
            const float v1 = v_s[c][tx * 4 + 1];
            const float v2 = v_s[c][tx * 4 + 2];
            const float v3 = v_s[c][tx * 4 + 3];
#pragma unroll
            for (int i = 0; i < 4; i++) {
                const float p = p_s[ty * 4 + i][c];
                o[i][0] += p * v0;
                o[i][1] += p * v1;
                o[i][2] += p * v2;
                o[i][3] += p * v3;
            }
        }
    }

    // epilogue: normalize, write out (S, B, E)
#pragma unroll
    for (int i = 0; i < 4; i++) {
        const float inv = 1.0f / l_r[i];
        const int s = q0 + ty * 4 + i;
        float4 r;
        r.x = o[i][0] * inv;
        r.y = o[i][1] * inv;
        r.z = o[i][2] * inv;
        r.w = o[i][3] * inv;
        *(float4*)(out + (size_t)s * (BATCH * EMB) + (size_t)b * EMB + h * HDIM + tx * 4) = r;
    }
}

extern "C" void kernel_launch(void* const* d_in, const int* in_sizes, int n_in,
                              void* d_out, int out_size) {
    (void)in_sizes; (void)n_in; (void)out_size;
    const float* X  = (const float*)d_in[0];
    const float* Wq = (const float*)d_in[1];
    const float* bq = (const float*)d_in[2];
    const float* Wk = (const float*)d_in[3];
    const float* bk = (const float*)d_in[4];
    const float* Wv = (const float*)d_in[5];
    const float* bv = (const float*)d_in[6];
    float* out = (float*)d_out;

    dim3 g1(SEQ * BATCH / 64, EMB / 64, 3);   // (128, 12, 3)
    qkv_gemm_kernel<<<g1, 256>>>(X, Wq, bq, Wk, bk, Wv, bv);

    dim3 g2(SEQ / 64, NHEAD, BATCH);          // (64, 12, 2)
    attn_kernel<<<g2, 256>>>(out);
}

// round 3
// speedup vs baseline: 1.8055x; 1.8055x over previous
#include <cuda_runtime.h>
#include <cuda_bf16.h>
#include <cstdint>

typedef unsigned long long u64;
typedef unsigned int u32;

#define SEQ   4096
#define BATCH 2
#define EMB   768
#define NHEAD 12
#define HDIM  64
#define HALFW 256
#define MROWS (SEQ * BATCH)   // 8192

// ---------------- device scratch ----------------
__device__ float g_qkv[3][(size_t)BATCH * NHEAD * SEQ * HDIM];
__device__ __nv_bfloat16 g_xhi[(size_t)MROWS * EMB];
__device__ __nv_bfloat16 g_xlo[(size_t)MROWS * EMB];
__device__ __nv_bfloat16 g_wth[3][(size_t)EMB * EMB];   // W^T hi  [n][k]
__device__ __nv_bfloat16 g_wtl[3][(size_t)EMB * EMB];   // W^T lo

// ---------------- PTX helpers (baseline sm_80-class only) ----------------
__device__ __forceinline__ u32 smem_u32(const void* p) {
    u32 a;
    asm("{ .reg .u64 t; cvta.to.shared.u64 t, %1; cvt.u32.u64 %0, t; }" : "=r"(a) : "l"(p));
    return a;
}
__device__ __forceinline__ void cp_async16(u32 dst, const void* src) {
    asm volatile("cp.async.cg.shared.global [%0], [%1], 16;" :: "r"(dst), "l"(src) : "memory");
}
__device__ __forceinline__ void cp_commit() {
    asm volatile("cp.async.commit_group;" ::: "memory");
}
template <int N>
__device__ __forceinline__ void cp_wait() {
    asm volatile("cp.async.wait_group %0;" :: "n"(N) : "memory");
}
__device__ __forceinline__ void ldmx4(u32* r, u32 addr) {
    asm volatile("ldmatrix.sync.aligned.m8n8.x4.shared.b16 {%0,%1,%2,%3}, [%4];"
                 : "=r"(r[0]), "=r"(r[1]), "=r"(r[2]), "=r"(r[3]) : "r"(addr));
}
__device__ __forceinline__ void mma16816(float* c, const u32* a, u32 b0, u32 b1) {
    asm volatile(
        "mma.sync.aligned.m16n8k16.row.col.f32.bf16.bf16.f32 "
        "{%0,%1,%2,%3}, {%4,%5,%6,%7}, {%8,%9}, {%0,%1,%2,%3};"
        : "+f"(c[0]), "+f"(c[1]), "+f"(c[2]), "+f"(c[3])
        : "r"(a[0]), "r"(a[1]), "r"(a[2]), "r"(a[3]), "r"(b0), "r"(b1));
}

// ---------------------------------------------------------------------------
// split X into bf16 hi + lo
// ---------------------------------------------------------------------------
__global__ __launch_bounds__(256) void split_x_kernel(const float* __restrict__ X) {
    const size_t i = (size_t)blockIdx.x * 256 + threadIdx.x;
    if (i >= (size_t)MROWS * EMB) return;
    const float x = X[i];
    const __nv_bfloat16 hi = __float2bfloat16(x);
    g_xhi[i] = hi;
    g_xlo[i] = __float2bfloat16(x - __bfloat162float(hi));
}

// ---------------------------------------------------------------------------
// transpose + split W: Wt[n][k] = W[k][n], hi/lo bf16
// ---------------------------------------------------------------------------
__global__ __launch_bounds__(256) void split_w_kernel(
    const float* __restrict__ Wq, const float* __restrict__ Wk,
    const float* __restrict__ Wv)
{
    __shared__ float t[32][33];
    const int z = blockIdx.z;
    const float* W = (z == 0) ? Wq : (z == 1) ? Wk : Wv;
    const int n0 = blockIdx.x * 32;
    const int k0 = blockIdx.y * 32;
    const int tx = threadIdx.x, ty = threadIdx.y;
#pragma unroll
    for (int i = 0; i < 4; i++) {
        const int kk = ty + i * 8;
        t[kk][tx] = W[(size_t)(k0 + kk) * EMB + n0 + tx];
    }
    __syncthreads();
#pragma unroll
    for (int i = 0; i < 4; i++) {
        const int nn = ty + i * 8;
        const float v = t[tx][nn];
        const __nv_bfloat16 hi = __float2bfloat16(v);
        const size_t idx = (size_t)(n0 + nn) * EMB + k0 + tx;
        g_wth[z][idx] = hi;
        g_wtl[z][idx] = __float2bfloat16(v - __bfloat162float(hi));
    }
}

// ---------------------------------------------------------------------------
// bf16 split-precision GEMM via mma.sync (HMMA.16816).
//   D = Ahi.Bhi^T + Ahi.Blo^T + Alo.Bhi^T  (+bias)*scale
// CTA tile 128x128, BK=32, 8 warps (2M x 4N), warp tile 64x32.
// Smem rows padded to 80B -> conflict-free ldmatrix. cp.async double buffer.
// ---------------------------------------------------------------------------
#define BK        32
#define ROWB      80                       // padded row bytes (32 bf16 -> 80B)
#define TILE_B    (128 * ROWB)             // 10240
#define STAGE_B   (4 * TILE_B)             // Ahi, Alo, Bhi, Blo = 40960
#define GEMM_SMEM (2 * STAGE_B)            // 81920
#define NCHUNK    (EMB / BK)               // 24

__global__ __launch_bounds__(256, 1)
void gemm_mma_kernel(const float* __restrict__ bq, const float* __restrict__ bk_,
                     const float* __restrict__ bv)
{
    extern __shared__ __align__(1024) char smem[];
    __shared__ float bias_sh[128];

    const int tid = threadIdx.x;
    const int wid = tid >> 5;
    const int lid = tid & 31;
    const int wm = wid >> 2;        // 0..1  (64-row slab)
    const int wn = wid & 3;         // 0..3  (32-col slab)
    const int which = blockIdx.z;
    const int m0 = blockIdx.x * 128;
    const int n0 = blockIdx.y * 128;

    const u32 sb = smem_u32(smem);

    const float* bias = (which == 0) ? bq : (which == 1) ? bk_ : bv;
    if (tid < 128) bias_sh[tid] = bias[n0 + tid];

    const __nv_bfloat16* srcA[2] = { g_xhi + (size_t)m0 * EMB, g_xlo + (size_t)m0 * EMB };
    const __nv_bfloat16* srcB[2] = { g_wth[which] + (size_t)n0 * EMB,
                                     g_wtl[which] + (size_t)n0 * EMB };

    // per-lane ldmatrix offsets (within a tile, excluding k-step advance)
    // A (x4): row = wm*64 + mi*16 + (l&7) + ((l>>3)&1)*8 ; col16 = (l>>4)
    u32 aoff[4];
#pragma unroll
    for (int mi = 0; mi < 4; mi++)
        aoff[mi] = (u32)((wm * 64 + mi * 16 + (lid & 7) + ((lid >> 3) & 1) * 8) * ROWB
                         + (lid >> 4) * 16);
    // B (x4 over two n8 tiles): mat=l>>3: row = wn*32 + j*16 + (mat>>1)*8 + (l&7); col16 = mat&1
    u32 boff[2];
#pragma unroll
    for (int j = 0; j < 2; j++)
        boff[j] = (u32)((wn * 32 + j * 16 + (((lid >> 3) >> 1) & 1) * 8 + (lid & 7)) * ROWB
                        + ((lid >> 3) & 1) * 16);

    float acc[4][4][4];
#pragma unroll
    for (int mi = 0; mi < 4; mi++)
#pragma unroll
        for (int ni = 0; ni < 4; ni++)
#pragma unroll
            for (int q = 0; q < 4; q++) acc[mi][ni][q] = 0.0f;

    // ---- async load of one K-chunk (4 tiles of 128 rows x 64B) ----
    auto load_chunk = [&](int c, int s) {
        const int k0 = c * BK;
        const u32 stage = sb + s * STAGE_B;
#pragma unroll
        for (int t = 0; t < 4; t++) {
            const __nv_bfloat16* src = (t < 2) ? srcA[t] : srcB[t - 2];
            const u32 tbase = stage + t * TILE_B;
#pragma unroll
            for (int i = 0; i < 2; i++) {
                const int g   = tid + i * 256;   // 0..511
                const int row = g >> 2;
                const int prt = g & 3;
                cp_async16(tbase + row * ROWB + prt * 16,
                           src + (size_t)row * EMB + k0 + prt * 8);
            }
        }
        cp_commit();
    };

    auto compute_chunk = [&](int s) {
        const u32 stage = sb + s * STAGE_B;
        const u32 aHi = stage + 0 * TILE_B, aLo = stage + 1 * TILE_B;
        const u32 bHi = stage + 2 * TILE_B, bLo = stage + 3 * TILE_B;
#pragma unroll
        for (int ks = 0; ks < 2; ks++) {
            const u32 kadv = ks * 32;     // 16 bf16 = 32B
            u32 ah[4][4], al[4][4], bh[2][4], bl[2][4];
#pragma unroll
            for (int mi = 0; mi < 4; mi++) {
                ldmx4(ah[mi], aHi + aoff[mi] + kadv);
                ldmx4(al[mi], aLo + aoff[mi] + kadv);
            }
#pragma unroll
            for (int j = 0; j < 2; j++) {
                ldmx4(bh[j], bHi + boff[j] + kadv);
                ldmx4(bl[j], bLo + boff[j] + kadv);
            }
#pragma unroll
            for (int mi = 0; mi < 4; mi++)
#pragma unroll
                for (int ni = 0; ni < 4; ni++) {
                    const int j = ni >> 1, e = (ni & 1) * 2;
                    mma16816(acc[mi][ni], ah[mi], bh[j][e], bh[j][e + 1]); // hi*hi
                    mma16816(acc[mi][ni], ah[mi], bl[j][e], bl[j][e + 1]); // hi*lo
                    mma16816(acc[mi][ni], al[mi], bh[j][e], bh[j][e + 1]); // lo*hi
                }
        }
    };

    load_chunk(0, 0);
    for (int c = 0; c < NCHUNK; c++) {
        if (c + 1 < NCHUNK) {
            load_chunk(c + 1, (c + 1) & 1);
            cp_wait<1>();
        } else {
            cp_wait<0>();
        }
        __syncthreads();
        compute_chunk(c & 1);
        __syncthreads();
    }

    // ---- epilogue: bias + scale, scatter to (B,H,S,D) ----
    const float scale = (which == 0) ? 0.125f : 1.0f;
    const int row_in_q = lid >> 2;        // 0..7
    const int col_pair = (lid & 3) * 2;   // 0,2,4,6
#pragma unroll
    for (int mi = 0; mi < 4; mi++) {
#pragma unroll
        for (int ni = 0; ni < 4; ni++) {
            const int ncol = wn * 32 + ni * 8 + col_pair;   // within CTA tile
            const int n = n0 + ncol;
            const int h = n >> 6;
            const int d = n & 63;
            const float b0v = bias_sh[ncol], b1v = bias_sh[ncol + 1];
#pragma unroll
            for (int half = 0; half < 2; half++) {
                const int m = m0 + wm * 64 + mi * 16 + row_in_q + half * 8;
                const int s_ = m >> 1;
                const int b_ = m & 1;
                float2 o;
                o.x = (acc[mi][ni][half * 2 + 0] + b0v) * scale;
                o.y = (acc[mi][ni][half * 2 + 1] + b1v) * scale;
                *(float2*)(g_qkv[which] + ((size_t)(b_ * NHEAD + h) * SEQ + s_) * HDIM + d) = o;
            }
        }
    }
}

// ---------------------------------------------------------------------------
// Kernel 2: banded local attention (unchanged).
// ---------------------------------------------------------------------------
__global__ __launch_bounds__(256) void attn_kernel(float* __restrict__ out)
{
    __shared__ __align__(16) float q_s[64][64];
    __shared__ __align__(16) float k_s[32][65];
    __shared__ __align__(16) float v_s[32][64];
    __shared__ __align__(16) float p_s[64][32];

    const int tid = threadIdx.x;
    const int ty = tid >> 4;
    const int tx = tid & 15;
    const int q0 = blockIdx.x * 64;
    const int h  = blockIdx.y;
    const int b  = blockIdx.z;

    const size_t bh = (size_t)(b * NHEAD + h) * SEQ * HDIM;
    const float* qg = g_qkv[0] + bh;
    const float* kg = g_qkv[1] + bh;
    const float* vg = g_qkv[2] + bh;

    for (int idx = tid; idx < 64 * 16; idx += 256) {
        const int row = idx >> 4;
        const int c4  = idx & 15;
        *(float4*)&q_s[row][c4 * 4] = *(const float4*)(qg + (size_t)(q0 + row) * HDIM + c4 * 4);
    }

    float o[4][4];
    float m_r[4], l_r[4];
#pragma unroll
    for (int i = 0; i < 4; i++) {
        m_r[i] = -1e30f;
        l_r[i] = 0.0f;
#pragma unroll
        for (int j = 0; j < 4; j++) o[i][j] = 0.0f;
    }

    for (int kt = q0 - HALFW; kt <= q0 + 288; kt += 32) {
        if (kt < 0 || kt >= SEQ) continue;
        __syncthreads();
        for (int idx = tid; idx < 32 * 16; idx += 256) {
            const int row = idx >> 4;
            const int c4  = idx & 15;
            const float4 kv = *(const float4*)(kg + (size_t)(kt + row) * HDIM + c4 * 4);
            k_s[row][c4 * 4 + 0] = kv.x;
            k_s[row][c4 * 4 + 1] = kv.y;
            k_s[row][c4 * 4 + 2] = kv.z;
            k_s[row][c4 * 4 + 3] = kv.w;
            *(float4*)&v_s[row][c4 * 4] = *(const float4*)(vg + (size_t)(kt + row) * HDIM + c4 * 4);
        }
        __syncthreads();

        float sc[4][2];
#pragma unroll
        for (int i = 0; i < 4; i++) { sc[i][0] = 0.0f; sc[i][1] = 0.0f; }
#pragma unroll 8
        for (int kk = 0; kk < HDIM; kk++) {
            const float kv0 = k_s[tx * 2 + 0][kk];
            const float kv1 = k_s[tx * 2 + 1][kk];
#pragma unroll
            for (int i = 0; i < 4; i++) {
                const float qv = q_s[ty * 4 + i][kk];
                sc[i][0] += qv * kv0;
                sc[i][1] += qv * kv1;
            }
        }

#pragma unroll
        for (int i = 0; i < 4; i++) {
            const int qa = q0 + ty * 4 + i;
#pragma unroll
            for (int j = 0; j < 2; j++) {
                const int d = (kt + tx * 2 + j) - qa;
                if (d < -HALFW || d > HALFW) sc[i][j] = -3.0e38f;
            }
            float tmax = fmaxf(sc[i][0], sc[i][1]);
#pragma unroll
            for (int off = 1; off < 16; off <<= 1)
                tmax = fmaxf(tmax, __shfl_xor_sync(0xffffffffu, tmax, off));
            const float newm = fmaxf(m_r[i], tmax);
            const float corr = __expf(m_r[i] - newm);
            const float p0 = __expf(sc[i][0] - newm);
            const float p1 = __expf(sc[i][1] - newm);
            float rs = p0 + p1;
#pragma unroll
            for (int off = 1; off < 16; off <<= 1)
                rs += __shfl_xor_sync(0xffffffffu, rs, off);
            l_r[i] = l_r[i] * corr + rs;
            m_r[i] = newm;
#pragma unroll
            for (int j2 = 0; j2 < 4; j2++) o[i][j2] *= corr;
            p_s[ty * 4 + i][tx * 2 + 0] = p0;
            p_s[ty * 4 + i][tx * 2 + 1] = p1;
        }
        __syncthreads();

#pragma unroll 8
        for (int c = 0; c < 32; c++) {
            const float v0 = v_s[c][tx * 4 + 0];
            const float v1 = v_s[c][tx * 4 + 1];
            const float v2 = v_s[c][tx * 4 + 2];
            const float v3 = v_s[c][tx * 4 + 3];
#pragma unroll
            for (int i = 0; i < 4; i++) {
                const float p = p_s[ty * 4 + i][c];
                o[i][0] += p * v0;
                o[i][1] += p * v1;
                o[i][2] += p * v2;
                o[i][3] += p * v3;
            }
        }
    }

#pragma unroll
    for (int i = 0; i < 4; i++) {
        const float inv = 1.0f / l_r[i];
        const int s = q0 + ty * 4 + i;
        float4 r;
        r.x = o[i][0] * inv;
        r.y = o[i][1] * inv;
        r.z = o[i][2] * inv;
        r.w = o[i][3] * inv;
        *(float4*)(out + (size_t)s * (BATCH * EMB) + (size_t)b * EMB + h * HDIM + tx * 4) = r;
    }
}

extern "C" void kernel_launch(void* const* d_in, const int* in_sizes, int n_in,
                              void* d_out, int out_size) {
    (void)in_sizes; (void)n_in; (void)out_size;
    const float* X  = (const float*)d_in[0];
    const float* Wq = (const float*)d_in[1];
    const float* bq = (const float*)d_in[2];
    const float* Wk = (const float*)d_in[3];
    const float* bk = (const float*)d_in[4];
    const float* Wv = (const float*)d_in[5];
    const float* bv = (const float*)d_in[6];
    float* out = (float*)d_out;

    static int attr_set = 0;
    if (!attr_set) {
        cudaFuncSetAttribute(gemm_mma_kernel,
                             cudaFuncAttributeMaxDynamicSharedMemorySize, GEMM_SMEM);
        attr_set = 1;
    }

    split_x_kernel<<<(MROWS * EMB + 255) / 256, 256>>>(X);
    split_w_kernel<<<dim3(24, 24, 3), dim3(32, 8)>>>(Wq, Wk, Wv);

    dim3 gg(MROWS / 128, EMB / 128, 3);   // (64, 6, 3)
    gemm_mma_kernel<<<gg, 256, GEMM_SMEM>>>(bq, bk, bv);

    dim3 ga(SEQ / 64, NHEAD, BATCH);      // (64, 12, 2)
    attn_kernel<<<ga, 256>>>(out);
}

// round 4
// speedup vs baseline: 3.0957x; 1.7146x over previous
#include <cuda_runtime.h>
#include <cuda_bf16.h>
#include <cstdint>

typedef unsigned long long u64;
typedef unsigned int u32;

#define SEQ   4096
#define BATCH 2
#define EMB   768
#define NHEAD 12
#define HDIM  64
#define HALFW 256
#define MROWS (SEQ * BATCH)   // 8192

// ---------------- device scratch ----------------
// Q/K/V stored as bf16 hi/lo residual pairs, layout (B, H, S, D)
__device__ __nv_bfloat16 g_qkvh[3][(size_t)BATCH * NHEAD * SEQ * HDIM];
__device__ __nv_bfloat16 g_qkvl[3][(size_t)BATCH * NHEAD * SEQ * HDIM];
__device__ __nv_bfloat16 g_xhi[(size_t)MROWS * EMB];
__device__ __nv_bfloat16 g_xlo[(size_t)MROWS * EMB];
__device__ __nv_bfloat16 g_wth[3][(size_t)EMB * EMB];   // W^T hi  [n][k]
__device__ __nv_bfloat16 g_wtl[3][(size_t)EMB * EMB];   // W^T lo

// ---------------- PTX helpers ----------------
__device__ __forceinline__ u32 smem_u32(const void* p) {
    u32 a;
    asm("{ .reg .u64 t; cvta.to.shared.u64 t, %1; cvt.u32.u64 %0, t; }" : "=r"(a) : "l"(p));
    return a;
}
__device__ __forceinline__ void cp_async16(u32 dst, const void* src) {
    asm volatile("cp.async.cg.shared.global [%0], [%1], 16;" :: "r"(dst), "l"(src) : "memory");
}
__device__ __forceinline__ void cp_commit() {
    asm volatile("cp.async.commit_group;" ::: "memory");
}
template <int N>
__device__ __forceinline__ void cp_wait() {
    asm volatile("cp.async.wait_group %0;" :: "n"(N) : "memory");
}
__device__ __forceinline__ void ldmx4(u32* r, u32 addr) {
    asm volatile("ldmatrix.sync.aligned.m8n8.x4.shared.b16 {%0,%1,%2,%3}, [%4];"
                 : "=r"(r[0]), "=r"(r[1]), "=r"(r[2]), "=r"(r[3]) : "r"(addr));
}
__device__ __forceinline__ void ldmx4t(u32* r, u32 addr) {
    asm volatile("ldmatrix.sync.aligned.m8n8.x4.trans.shared.b16 {%0,%1,%2,%3}, [%4];"
                 : "=r"(r[0]), "=r"(r[1]), "=r"(r[2]), "=r"(r[3]) : "r"(addr));
}
__device__ __forceinline__ void mma16816(float* c, const u32* a, u32 b0, u32 b1) {
    asm volatile(
        "mma.sync.aligned.m16n8k16.row.col.f32.bf16.bf16.f32 "
        "{%0,%1,%2,%3}, {%4,%5,%6,%7}, {%8,%9}, {%0,%1,%2,%3};"
        : "+f"(c[0]), "+f"(c[1]), "+f"(c[2]), "+f"(c[3])
        : "r"(a[0]), "r"(a[1]), "r"(a[2]), "r"(a[3]), "r"(b0), "r"(b1));
}
// pack2: lo -> low half, hi -> high half
__device__ __forceinline__ u32 pack_bf(float lo, float hi) {
    u32 r;
    asm("cvt.rn.bf16x2.f32 %0, %1, %2;" : "=r"(r) : "f"(hi), "f"(lo));
    return r;
}
__device__ __forceinline__ void split_pair(float p0, float p1, u32& h, u32& l) {
    h = pack_bf(p0, p1);
    const float h0 = __uint_as_float(h << 16);
    const float h1 = __uint_as_float(h & 0xffff0000u);
    l = pack_bf(p0 - h0, p1 - h1);
}

// ---------------------------------------------------------------------------
// split X into bf16 hi + lo
// ---------------------------------------------------------------------------
__global__ __launch_bounds__(256) void split_x_kernel(const float* __restrict__ X) {
    const size_t i = (size_t)blockIdx.x * 256 + threadIdx.x;
    if (i >= (size_t)MROWS * EMB) return;
    const float x = X[i];
    const __nv_bfloat16 hi = __float2bfloat16(x);
    g_xhi[i] = hi;
    g_xlo[i] = __float2bfloat16(x - __bfloat162float(hi));
}

// ---------------------------------------------------------------------------
// transpose + split W
// ---------------------------------------------------------------------------
__global__ __launch_bounds__(256) void split_w_kernel(
    const float* __restrict__ Wq, const float* __restrict__ Wk,
    const float* __restrict__ Wv)
{
    __shared__ float t[32][33];
    const int z = blockIdx.z;
    const float* W = (z == 0) ? Wq : (z == 1) ? Wk : Wv;
    const int n0 = blockIdx.x * 32;
    const int k0 = blockIdx.y * 32;
    const int tx = threadIdx.x, ty = threadIdx.y;
#pragma unroll
    for (int i = 0; i < 4; i++) {
        const int kk = ty + i * 8;
        t[kk][tx] = W[(size_t)(k0 + kk) * EMB + n0 + tx];
    }
    __syncthreads();
#pragma unroll
    for (int i = 0; i < 4; i++) {
        const int nn = ty + i * 8;
        const float v = t[tx][nn];
        const __nv_bfloat16 hi = __float2bfloat16(v);
        const size_t idx = (size_t)(n0 + nn) * EMB + k0 + tx;
        g_wth[z][idx] = hi;
        g_wtl[z][idx] = __float2bfloat16(v - __bfloat162float(hi));
    }
}

// ---------------------------------------------------------------------------
// bf16 split-precision QKV GEMM via mma.sync (unchanged core from R3),
// epilogue now writes bf16 hi/lo residual pairs.
// ---------------------------------------------------------------------------
#define BK        32
#define ROWB      80
#define TILE_B    (128 * ROWB)
#define STAGE_B   (4 * TILE_B)
#define GEMM_SMEM (2 * STAGE_B)
#define NCHUNK    (EMB / BK)

__global__ __launch_bounds__(256, 1)
void gemm_mma_kernel(const float* __restrict__ bq, const float* __restrict__ bk_,
                     const float* __restrict__ bv)
{
    extern __shared__ __align__(1024) char smem[];
    __shared__ float bias_sh[128];

    const int tid = threadIdx.x;
    const int wid = tid >> 5;
    const int lid = tid & 31;
    const int wm = wid >> 2;
    const int wn = wid & 3;
    const int which = blockIdx.z;
    const int m0 = blockIdx.x * 128;
    const int n0 = blockIdx.y * 128;

    const u32 sb = smem_u32(smem);

    const float* bias = (which == 0) ? bq : (which == 1) ? bk_ : bv;
    if (tid < 128) bias_sh[tid] = bias[n0 + tid];

    const __nv_bfloat16* srcA[2] = { g_xhi + (size_t)m0 * EMB, g_xlo + (size_t)m0 * EMB };
    const __nv_bfloat16* srcB[2] = { g_wth[which] + (size_t)n0 * EMB,
                                     g_wtl[which] + (size_t)n0 * EMB };

    u32 aoff[4];
#pragma unroll
    for (int mi = 0; mi < 4; mi++)
        aoff[mi] = (u32)((wm * 64 + mi * 16 + (lid & 7) + ((lid >> 3) & 1) * 8) * ROWB
                         + (lid >> 4) * 16);
    u32 boff[2];
#pragma unroll
    for (int j = 0; j < 2; j++)
        boff[j] = (u32)((wn * 32 + j * 16 + (((lid >> 3) >> 1) & 1) * 8 + (lid & 7)) * ROWB
                        + ((lid >> 3) & 1) * 16);

    float acc[4][4][4];
#pragma unroll
    for (int mi = 0; mi < 4; mi++)
#pragma unroll
        for (int ni = 0; ni < 4; ni++)
#pragma unroll
            for (int q = 0; q < 4; q++) acc[mi][ni][q] = 0.0f;

    auto load_chunk = [&](int c, int s) {
        const int k0 = c * BK;
        const u32 stage = sb + s * STAGE_B;
#pragma unroll
        for (int t = 0; t < 4; t++) {
            const __nv_bfloat16* src = (t < 2) ? srcA[t] : srcB[t - 2];
            const u32 tbase = stage + t * TILE_B;
#pragma unroll
            for (int i = 0; i < 2; i++) {
                const int g   = tid + i * 256;
                const int row = g >> 2;
                const int prt = g & 3;
                cp_async16(tbase + row * ROWB + prt * 16,
                           src + (size_t)row * EMB + k0 + prt * 8);
            }
        }
        cp_commit();
    };

    auto compute_chunk = [&](int s) {
        const u32 stage = sb + s * STAGE_B;
        const u32 aHi = stage + 0 * TILE_B, aLo = stage + 1 * TILE_B;
        const u32 bHi = stage + 2 * TILE_B, bLo = stage + 3 * TILE_B;
#pragma unroll
        for (int ks = 0; ks < 2; ks++) {
            const u32 kadv = ks * 32;
            u32 ah[4][4], al[4][4], bh[2][4], bl[2][4];
#pragma unroll
            for (int mi = 0; mi < 4; mi++) {
                ldmx4(ah[mi], aHi + aoff[mi] + kadv);
                ldmx4(al[mi], aLo + aoff[mi] + kadv);
            }
#pragma unroll
            for (int j = 0; j < 2; j++) {
                ldmx4(bh[j], bHi + boff[j] + kadv);
                ldmx4(bl[j], bLo + boff[j] + kadv);
            }
#pragma unroll
            for (int mi = 0; mi < 4; mi++)
#pragma unroll
                for (int ni = 0; ni < 4; ni++) {
                    const int j = ni >> 1, e = (ni & 1) * 2;
                    mma16816(acc[mi][ni], ah[mi], bh[j][e], bh[j][e + 1]);
                    mma16816(acc[mi][ni], ah[mi], bl[j][e], bl[j][e + 1]);
                    mma16816(acc[mi][ni], al[mi], bh[j][e], bh[j][e + 1]);
                }
        }
    };

    load_chunk(0, 0);
    for (int c = 0; c < NCHUNK; c++) {
        if (c + 1 < NCHUNK) {
            load_chunk(c + 1, (c + 1) & 1);
            cp_wait<1>();
        } else {
            cp_wait<0>();
        }
        __syncthreads();
        compute_chunk(c & 1);
        __syncthreads();
    }

    // epilogue: bias + scale, split to bf16 hi/lo, scatter to (B,H,S,D)
    const float scale = (which == 0) ? 0.125f : 1.0f;
    const int row_in_q = lid >> 2;
    const int col_pair = (lid & 3) * 2;
#pragma unroll
    for (int mi = 0; mi < 4; mi++) {
#pragma unroll
        for (int ni = 0; ni < 4; ni++) {
            const int ncol = wn * 32 + ni * 8 + col_pair;
            const int n = n0 + ncol;
            const int h = n >> 6;
            const int d = n & 63;
            const float b0v = bias_sh[ncol], b1v = bias_sh[ncol + 1];
#pragma unroll
            for (int half = 0; half < 2; half++) {
                const int m = m0 + wm * 64 + mi * 16 + row_in_q + half * 8;
                const int s_ = m >> 1;
                const int b_ = m & 1;
                const float v0 = (acc[mi][ni][half * 2 + 0] + b0v) * scale;
                const float v1 = (acc[mi][ni][half * 2 + 1] + b1v) * scale;
                u32 hpk, lpk;
                split_pair(v0, v1, hpk, lpk);
                const size_t idx = ((size_t)(b_ * NHEAD + h) * SEQ + s_) * HDIM + d;
                *(u32*)(g_qkvh[which] + idx) = hpk;
                *(u32*)(g_qkvl[which] + idx) = lpk;
            }
        }
    }
}

// ---------------------------------------------------------------------------
// Banded local attention via mma.sync, split precision throughout.
// CTA = 64 queries of one (b,h); 4 warps x 16 rows; k-tiles of 64 keys.
// ---------------------------------------------------------------------------
#define AROWB   144                          // 64 bf16 = 128B, padded to 144B
#define ATILE   (64 * AROWB)                 // 9216
#define AQ_B    (2 * ATILE)                  // Qhi, Qlo
#define ASTAGE  (4 * ATILE)                  // Khi, Klo, Vhi, Vlo
#define AT_SMEM (AQ_B + 2 * ASTAGE)          // 92160

__global__ __launch_bounds__(128, 1)
void attn_mma_kernel(float* __restrict__ out)
{
    extern __shared__ __align__(1024) char smem[];
    const int tid = threadIdx.x;
    const int wid = tid >> 5;
    const int lid = tid & 31;
    const int q0 = blockIdx.x * 64;
    const int h  = blockIdx.y;
    const int b  = blockIdx.z;
    const size_t bh = (size_t)(b * NHEAD + h) * SEQ * HDIM;

    const u32 sb = smem_u32(smem);

    // valid k-tile range
    int kt0 = q0 - HALFW; if (kt0 < 0) kt0 = 0;
    int kt1 = q0 + HALFW; if (kt1 > SEQ - 64) kt1 = SEQ - 64;
    const int T = (kt1 - kt0) / 64 + 1;

    // ---- loaders (cp.async 16B) ----
    auto load_q = [&] {
#pragma unroll
        for (int tq = 0; tq < 2; tq++) {
            const __nv_bfloat16* src =
                ((tq == 0) ? g_qkvh[0] : g_qkvl[0]) + bh + (size_t)q0 * HDIM;
            const u32 dstb = sb + tq * ATILE;
#pragma unroll
            for (int i = 0; i < 4; i++) {
                const int g = tid + i * 128;
                const int row = g >> 3, c = g & 7;
                cp_async16(dstb + row * AROWB + c * 16, src + row * HDIM + c * 8);
            }
        }
    };
    auto load_kv = [&](int t, int s) {
        const int kt = kt0 + t * 64;
        const u32 stb = sb + AQ_B + s * ASTAGE;
        const __nv_bfloat16* srcs[4] = {
            g_qkvh[1] + bh + (size_t)kt * HDIM, g_qkvl[1] + bh + (size_t)kt * HDIM,
            g_qkvh[2] + bh + (size_t)kt * HDIM, g_qkvl[2] + bh + (size_t)kt * HDIM };
#pragma unroll
        for (int tt = 0; tt < 4; tt++) {
            const u32 dstb = stb + tt * ATILE;
#pragma unroll
            for (int i = 0; i < 4; i++) {
                const int g = tid + i * 128;
                const int row = g >> 3, c = g & 7;
                cp_async16(dstb + row * AROWB + c * 16, srcs[tt] + row * HDIM + c * 8);
            }
        }
    };

    load_q();
    load_kv(0, 0);
    cp_commit();

    // per-lane ldmatrix offsets
    const u32 a_off = (u32)((wid * 16 + (lid & 7) + ((lid >> 3) & 1) * 8) * AROWB
                            + (lid >> 4) * 16);                       // Q (A, non-trans)
    u32 kb_off[4];
#pragma unroll
    for (int p = 0; p < 4; p++)
        kb_off[p] = (u32)((16 * p + ((lid >> 4) & 1) * 8 + (lid & 7)) * AROWB
                          + ((lid >> 3) & 1) * 16);                   // K (B, non-trans)
    const u32 v_off = (u32)((lid & 15) * AROWB + (lid >> 4) * 16);    // V (B, trans)

    u32 qf[2][4][4];          // [hi/lo][kstep][reg]
    float o[8][4];
    float m_r[2] = { -1e30f, -1e30f };
    float l_r[2] = { 0.0f, 0.0f };
#pragma unroll
    for (int ni = 0; ni < 8; ni++)
#pragma unroll
        for (int e = 0; e < 4; e++) o[ni][e] = 0.0f;

    const int r_lane = lid >> 2;
    const int c_lane = (lid & 3) * 2;

    for (int t = 0; t < T; t++) {
        if (t + 1 < T) {
            load_kv(t + 1, (t + 1) & 1);
            cp_commit();
            cp_wait<1>();
        } else {
            cp_wait<0>();
        }
        __syncthreads();

        if (t == 0) {
#pragma unroll
            for (int ks = 0; ks < 4; ks++) {
                ldmx4(qf[0][ks], sb + 0 * ATILE + a_off + ks * 32);
                ldmx4(qf[1][ks], sb + 1 * ATILE + a_off + ks * 32);
            }
        }

        const int kt = kt0 + t * 64;
        const u32 st = sb + AQ_B + (t & 1) * ASTAGE;
        const u32 kHi = st + 0 * ATILE, kLo = st + 1 * ATILE;
        const u32 vHi = st + 2 * ATILE, vLo = st + 3 * ATILE;

        // ---- scores ----
        float sc[8][4];
#pragma unroll
        for (int ni = 0; ni < 8; ni++)
#pragma unroll
            for (int e = 0; e < 4; e++) sc[ni][e] = 0.0f;

#pragma unroll
        for (int ks = 0; ks < 4; ks++) {
#pragma unroll
            for (int p = 0; p < 4; p++) {
                u32 bh4[4], bl4[4];
                ldmx4(bh4, kHi + kb_off[p] + ks * 32);
                ldmx4(bl4, kLo + kb_off[p] + ks * 32);
                mma16816(sc[2 * p + 0], qf[0][ks], bh4[0], bh4[1]);
                mma16816(sc[2 * p + 1], qf[0][ks], bh4[2], bh4[3]);
                mma16816(sc[2 * p + 0], qf[0][ks], bl4[0], bl4[1]);
                mma16816(sc[2 * p + 1], qf[0][ks], bl4[2], bl4[3]);
                mma16816(sc[2 * p + 0], qf[1][ks], bh4[0], bh4[1]);
                mma16816(sc[2 * p + 1], qf[1][ks], bh4[2], bh4[3]);
            }
        }

        // ---- band mask (only first/last tile of the full window) ----
        if (kt == q0 - HALFW || kt == q0 + HALFW) {
#pragma unroll
            for (int ni = 0; ni < 8; ni++)
#pragma unroll
                for (int e = 0; e < 4; e++) {
                    const int kc = kt + ni * 8 + c_lane + (e & 1);
                    const int qa = q0 + wid * 16 + r_lane + ((e >> 1) << 3);
                    const int d = kc - qa;
                    if (d < -HALFW || d > HALFW) sc[ni][e] = -3.0e38f;
                }
        }

        // ---- online softmax ----
        float mx0 = -3.0e38f, mx1 = -3.0e38f;
#pragma unroll
        for (int ni = 0; ni < 8; ni++) {
            mx0 = fmaxf(mx0, fmaxf(sc[ni][0], sc[ni][1]));
            mx1 = fmaxf(mx1, fmaxf(sc[ni][2], sc[ni][3]));
        }
        mx0 = fmaxf(mx0, __shfl_xor_sync(0xffffffffu, mx0, 1));
        mx0 = fmaxf(mx0, __shfl_xor_sync(0xffffffffu, mx0, 2));
        mx1 = fmaxf(mx1, __shfl_xor_sync(0xffffffffu, mx1, 1));
        mx1 = fmaxf(mx1, __shfl_xor_sync(0xffffffffu, mx1, 2));

        const float nm0 = fmaxf(m_r[0], mx0);
        const float nm1 = fmaxf(m_r[1], mx1);
        const float c0 = __expf(m_r[0] - nm0);
        const float c1 = __expf(m_r[1] - nm1);
        float s0 = 0.0f, s1 = 0.0f;
#pragma unroll
        for (int ni = 0; ni < 8; ni++) {
            sc[ni][0] = __expf(sc[ni][0] - nm0); s0 += sc[ni][0];
            sc[ni][1] = __expf(sc[ni][1] - nm0); s0 += sc[ni][1];
            sc[ni][2] = __expf(sc[ni][2] - nm1); s1 += sc[ni][2];
            sc[ni][3] = __expf(sc[ni][3] - nm1); s1 += sc[ni][3];
        }
        s0 += __shfl_xor_sync(0xffffffffu, s0, 1);
        s0 += __shfl_xor_sync(0xffffffffu, s0, 2);
        s1 += __shfl_xor_sync(0xffffffffu, s1, 1);
        s1 += __shfl_xor_sync(0xffffffffu, s1, 2);
        l_r[0] = l_r[0] * c0 + s0; m_r[0] = nm0;
        l_r[1] = l_r[1] * c1 + s1; m_r[1] = nm1;
#pragma unroll
        for (int ni = 0; ni < 8; ni++) {
            o[ni][0] *= c0; o[ni][1] *= c0;
            o[ni][2] *= c1; o[ni][3] *= c1;
        }

        // ---- PV: P passes fragment-to-fragment into the A operand ----
#pragma unroll
        for (int ks = 0; ks < 4; ks++) {
            u32 ph[4], pl[4];
            split_pair(sc[2 * ks + 0][0], sc[2 * ks + 0][1], ph[0], pl[0]);
            split_pair(sc[2 * ks + 0][2], sc[2 * ks + 0][3], ph[1], pl[1]);
            split_pair(sc[2 * ks + 1][0], sc[2 * ks + 1][1], ph[2], pl[2]);
            split_pair(sc[2 * ks + 1][2], sc[2 * ks + 1][3], ph[3], pl[3]);
#pragma unroll
            for (int p = 0; p < 4; p++) {
                u32 vh4[4], vl4[4];
                ldmx4t(vh4, vHi + v_off + ks * 16 * AROWB + p * 32);
                ldmx4t(vl4, vLo + v_off + ks * 16 * AROWB + p * 32);
                mma16816(o[2 * p + 0], ph, vh4[0], vh4[1]);
                mma16816(o[2 * p + 1], ph, vh4[2], vh4[3]);
                mma16816(o[2 * p + 0], ph, vl4[0], vl4[1]);
                mma16816(o[2 * p + 1], ph, vl4[2], vl4[3]);
                mma16816(o[2 * p + 0], pl, vh4[0], vh4[1]);
                mma16816(o[2 * p + 1], pl, vh4[2], vh4[3]);
            }
        }
        __syncthreads();
    }

    // ---- epilogue: normalize + write (S, B, E) ----
    const float inv0 = 1.0f / l_r[0];
    const float inv1 = 1.0f / l_r[1];
    const int s_row0 = q0 + wid * 16 + r_lane;
#pragma unroll
    for (int ni = 0; ni < 8; ni++) {
        const int dcol = ni * 8 + c_lane;
        const size_t base = (size_t)b * EMB + h * HDIM + dcol;
        float2 r0, r1;
        r0.x = o[ni][0] * inv0; r0.y = o[ni][1] * inv0;
        r1.x = o[ni][2] * inv1; r1.y = o[ni][3] * inv1;
        *(float2*)(out + (size_t)s_row0 * (BATCH * EMB) + base) = r0;
        *(float2*)(out + (size_t)(s_row0 + 8) * (BATCH * EMB) + base) = r1;
    }
}

extern "C" void kernel_launch(void* const* d_in, const int* in_sizes, int n_in,
                              void* d_out, int out_size) {
    (void)in_sizes; (void)n_in; (void)out_size;
    const float* X  = (const float*)d_in[0];
    const float* Wq = (const float*)d_in[1];
    const float* bq = (const float*)d_in[2];
    const float* Wk = (const float*)d_in[3];
    const float* bk = (const float*)d_in[4];
    const float* Wv = (const float*)d_in[5];
    const float* bv = (const float*)d_in[6];
    float* out = (float*)d_out;

    static int attr_set = 0;
    if (!attr_set) {
        cudaFuncSetAttribute(gemm_mma_kernel,
                             cudaFuncAttributeMaxDynamicSharedMemorySize, GEMM_SMEM);
        cudaFuncSetAttribute(attn_mma_kernel,
                             cudaFuncAttributeMaxDynamicSharedMemorySize, AT_SMEM);
        attr_set = 1;
    }

    split_x_kernel<<<(MROWS * EMB + 255) / 256, 256>>>(X);
    split_w_kernel<<<dim3(24, 24, 3), dim3(32, 8)>>>(Wq, Wk, Wv);

    dim3 gg(MROWS / 128, EMB / 128, 3);   // (64, 6, 3)
    gemm_mma_kernel<<<gg, 256, GEMM_SMEM>>>(bq, bk, bv);

    dim3 ga(SEQ / 64, NHEAD, BATCH);      // (64, 12, 2)
    attn_mma_kernel<<<ga, 128, AT_SMEM>>>(out);
}